// round 17
// baseline (speedup 1.0000x reference)
#include <cuda_runtime.h>
#include <cstdint>

#define Bv 8192
#define Mv 512
#define Ov 128
#define NCONC 296   // 148 SMs x 2 CTAs/SM = one wave

// ---- smem byte offsets ----
#define SM_XH   0        // x bf16: 512 rows * 128B (chunk-XOR swizzled) = 65536
#define SM_LN   65536    // lam^T bf16 (o-row-permuted): 128 rows * 128B = 16384
#define SM_SRED 81920    // 16 x 64 f32 partial column sums = 4096
#define SM_POOL 86016    // pooled[128] f32 = 512
#define SMEM_BYTES 86528

__device__ __forceinline__ uint32_t cvta_smem(const void* p) {
    uint32_t a;
    asm("{ .reg .u64 t; cvta.to.shared.u64 t, %1; cvt.u32.u64 %0, t; }" : "=r"(a) : "l"(p));
    return a;
}

__device__ __forceinline__ uint32_t pack_bf16x2(float lo, float hi) {
    uint32_t r;
    asm("cvt.rn.bf16x2.f32 %0, %1, %2;" : "=r"(r) : "f"(hi), "f"(lo));
    return r;
}

__device__ __forceinline__ void ldsm4(uint32_t addr, uint32_t r[4]) {
    asm volatile("ldmatrix.sync.aligned.m8n8.x4.shared.b16 {%0,%1,%2,%3}, [%4];"
        : "=r"(r[0]), "=r"(r[1]), "=r"(r[2]), "=r"(r[3]) : "r"(addr));
}

__device__ __forceinline__ void hmma(float d[4], const uint32_t a[4], const uint32_t b[2]) {
    asm volatile("mma.sync.aligned.m16n8k16.row.col.f32.bf16.bf16.f32 "
        "{%0,%1,%2,%3}, {%4,%5,%6,%7}, {%8,%9}, {%0,%1,%2,%3};"
        : "+f"(d[0]), "+f"(d[1]), "+f"(d[2]), "+f"(d[3])
        : "r"(a[0]), "r"(a[1]), "r"(a[2]), "r"(a[3]), "r"(b[0]), "r"(b[1]));
}

__device__ __forceinline__ float4 ldg_cs4(const float4* p) {
    float4 v;
    asm volatile("ld.global.cs.v4.f32 {%0,%1,%2,%3}, [%4];"
        : "=f"(v.x), "=f"(v.y), "=f"(v.z), "=f"(v.w) : "l"(p));
    return v;
}

// 256-bit streaming store (v8.b32 proven on this toolchain for ld; st same grammar)
__device__ __forceinline__ void stg_cs8(float* p,
    float v0, float v1, float v2, float v3,
    float v4, float v5, float v6, float v7)
{
    asm volatile("st.global.cs.v8.b32 [%0], {%1,%2,%3,%4,%5,%6,%7,%8};"
        :: "l"(p),
           "r"(__float_as_uint(v0)), "r"(__float_as_uint(v1)),
           "r"(__float_as_uint(v2)), "r"(__float_as_uint(v3)),
           "r"(__float_as_uint(v4)), "r"(__float_as_uint(v5)),
           "r"(__float_as_uint(v6)), "r"(__float_as_uint(v7))
        : "memory");
}

// forced L2 fill of next wave's x (evict_last survives streaming stores)
__device__ __forceinline__ void l2fill(const void* p) {
    uint32_t r0, r1, r2, r3, r4, r5, r6, r7;
    asm volatile("ld.global.L2::evict_last.v8.b32 {%0,%1,%2,%3,%4,%5,%6,%7}, [%8];"
        : "=r"(r0), "=r"(r1), "=r"(r2), "=r"(r3),
          "=r"(r4), "=r"(r5), "=r"(r6), "=r"(r7)
        : "l"(p));
}

extern __shared__ char smem[];

__global__ __launch_bounds__(256, 2)
void eq_mma14_kernel(const float* __restrict__ x,
                     const float* __restrict__ lam,
                     const float* __restrict__ gam,
                     float* __restrict__ out)
{
    const uint32_t sb = cvta_smem(smem);
    const int t = threadIdx.x;
    const int b = blockIdx.x;
    const int w = t >> 5, lane = t & 31, g = lane >> 2, tg = lane & 3;

    // ---- Phase A: x[b] fp32 -> bf16 smem (swizzled) + partial column sums ----
    {
        const float4* xg = (const float4*)(x + (size_t)b * (Mv * 64));
        const int f4 = t & 15;
        const int tm = t >> 4;
        const int chunk = f4 >> 1, half = f4 & 1;
        float4 s4 = make_float4(0.f, 0.f, 0.f, 0.f);
        #pragma unroll 8
        for (int i = 0; i < 32; i++) {
            const int m = tm + 16 * i;
            const float4 v = ldg_cs4(&xg[m * 16 + f4]);
            s4.x += v.x; s4.y += v.y; s4.z += v.z; s4.w += v.w;
            const uint32_t h01 = pack_bf16x2(v.x, v.y);
            const uint32_t h23 = pack_bf16x2(v.z, v.w);
            const uint32_t off = (uint32_t)(m * 128 + ((chunk ^ (m & 7)) << 4) + half * 8);
            *(uint2*)(smem + SM_XH + off) = make_uint2(h01, h23);
        }
        *(float4*)(smem + SM_SRED + (tm * 64 + f4 * 4) * 4) = s4;
    }

    // ---- force next wave's x[b+NCONC] into L2 ----
    if (b + NCONC < Bv) {
        const char* nx = (const char*)(x + (size_t)(b + NCONC) * (Mv * 64));
        #pragma unroll
        for (int j = 0; j < 4; j++)
            l2fill(nx + (t + 256 * j) * 128);
    }

    // ---- Phase B: lam^T -> bf16 smem, o-row-permuted within 32-row super-groups
    // real col o -> phys row: thread tg owns 8 contiguous real cols per 32-group.
    {
        const int o = t & 127;
        const int r5 = o & 31;
        const int orow = (o & ~31) | ((r5 & 4) << 2) | ((r5 & 2) << 2)
                       | ((r5 >> 3) << 1) | (r5 & 1);
        const int q = t >> 7;
        #pragma unroll 4
        for (int j = 0; j < 16; j++) {
            const int fp = q * 16 + j;
            const float v0 = lam[(2 * fp) * Ov + o];
            const float v1 = lam[(2 * fp + 1) * Ov + o];
            const uint32_t h = pack_bf16x2(v0, v1);
            const uint32_t off = (uint32_t)(orow * 128
                + (((fp >> 2) ^ (orow & 7)) << 4) + (fp & 3) * 4);
            *(uint32_t*)(smem + SM_LN + off) = h;
        }
    }
    __syncthreads();

    // ---- finalize s[f] = sum_m x[m,f] ----
    if (t < 64) {
        float v = 0.f;
        #pragma unroll
        for (int r = 0; r < 16; r++)
            v += *(const float*)(smem + SM_SRED + (r * 64 + t) * 4);
        *(float*)(smem + SM_SRED + t * 4) = v;
    }
    __syncthreads();

    // ---- pooled[o] = sum_f s[f] * gam[f,o] (exact fp32) ----
    if (t < 128) {
        float p = 0.f;
        #pragma unroll
        for (int f = 0; f < 64; f++)
            p += *(const float*)(smem + SM_SRED + f * 4) * gam[f * Ov + t];
        *(float*)(smem + SM_POOL + t * 4) = p;
    }
    __syncthreads();

    // ---- Main: per-warp 64 rows x 128 cols, two 32-row sub-passes ----
    const int am = lane & 15, acs = lane >> 4, asw = am & 7;
    const int bo = (lane & 7) | ((lane & 16) >> 1);
    const int bcs = (lane >> 3) & 1, bsw = bo & 7;
    const float* poolp = (const float*)(smem + SM_POOL);
    float* outb = out + (size_t)b * (Mv * Ov);

    #pragma unroll 1
    for (int mp = 0; mp < 2; mp++) {
        const int m0 = w * 64 + mp * 32;
        const uint32_t arow_off = (uint32_t)((m0 + am) * 128);

        uint32_t afr[4][2][4];
        #pragma unroll
        for (int k = 0; k < 4; k++) {
            const uint32_t aadr = sb + SM_XH + arow_off
                                + (uint32_t)((((k << 1) | acs) ^ asw) << 4);
            ldsm4(aadr, afr[k][0]);
            ldsm4(aadr + 16 * 128, afr[k][1]);
        }

        #pragma unroll 1
        for (int nh = 0; nh < 2; nh++) {
            const int o0 = nh * 64;
            float acc[2][8][4];
            #pragma unroll
            for (int i = 0; i < 2; i++)
                #pragma unroll
                for (int j = 0; j < 8; j++)
                    #pragma unroll
                    for (int c = 0; c < 4; c++)
                        acc[i][j][c] = 0.f;

            #pragma unroll
            for (int k = 0; k < 4; k++)
                #pragma unroll
                for (int np = 0; np < 4; np++) {
                    uint32_t bf[4];
                    ldsm4(sb + SM_LN + (uint32_t)((o0 + np * 16 + bo) * 128
                            + ((((k << 1) | bcs) ^ bsw) << 4)), bf);
                    hmma(acc[0][2 * np],     afr[k][0], bf);
                    hmma(acc[0][2 * np + 1], afr[k][0], bf + 2);
                    hmma(acc[1][2 * np],     afr[k][1], bf);
                    hmma(acc[1][2 * np + 1], afr[k][1], bf + 2);
                }

            // epilogue: q-th 32-col super-group -> 8 contiguous cols per thread
            // acc[mt][4q+0..3]: pairs (np=2q pair0/1, np=2q+1 pair0/1)
            //   regs [0],[1] -> row g; regs [2],[3] -> row g+8
            #pragma unroll
            for (int q = 0; q < 2; q++) {
                const int col = o0 + q * 32 + 8 * tg;
                const float4 plA = *(const float4*)&poolp[col];
                const float4 plB = *(const float4*)&poolp[col + 4];
                #pragma unroll
                for (int mt = 0; mt < 2; mt++) {
                    const float* A0 = acc[mt][4 * q];
                    const float* A1 = acc[mt][4 * q + 1];
                    const float* B0 = acc[mt][4 * q + 2];
                    const float* B1 = acc[mt][4 * q + 3];
                    float* r0 = outb + (size_t)(m0 + mt * 16 + g) * Ov + col;
                    stg_cs8(r0,
                        fmaxf(A0[0] - plA.x, 0.f), fmaxf(A0[1] - plA.y, 0.f),
                        fmaxf(A1[0] - plA.z, 0.f), fmaxf(A1[1] - plA.w, 0.f),
                        fmaxf(B0[0] - plB.x, 0.f), fmaxf(B0[1] - plB.y, 0.f),
                        fmaxf(B1[0] - plB.z, 0.f), fmaxf(B1[1] - plB.w, 0.f));
                    stg_cs8(r0 + 8 * Ov,
                        fmaxf(A0[2] - plA.x, 0.f), fmaxf(A0[3] - plA.y, 0.f),
                        fmaxf(A1[2] - plA.z, 0.f), fmaxf(A1[3] - plA.w, 0.f),
                        fmaxf(B0[2] - plB.x, 0.f), fmaxf(B0[3] - plB.y, 0.f),
                        fmaxf(B1[2] - plB.z, 0.f), fmaxf(B1[3] - plB.w, 0.f));
                }
            }
        }
    }
}

extern "C" void kernel_launch(void* const* d_in, const int* in_sizes, int n_in,
                              void* d_out, int out_size)
{
    (void)in_sizes; (void)n_in; (void)out_size;
    const float* x   = (const float*)d_in[0];
    const float* lam = (const float*)d_in[1];
    const float* gam = (const float*)d_in[2];
    float* out = (float*)d_out;

    cudaFuncSetAttribute(eq_mma14_kernel, cudaFuncAttributeMaxDynamicSharedMemorySize,
                         SMEM_BYTES);
    eq_mma14_kernel<<<Bv, 256, SMEM_BYTES>>>(x, lam, gam, out);
}